// round 1
// baseline (speedup 1.0000x reference)
#include <cuda_runtime.h>
#include <cuda_bf16.h>

// Problem constants
#define BATCH 4
#define SEQ   1024
#define CDIM  768
#define NHEAD 12
#define HDIM  64
#define RTOT  (BATCH * SEQ)          // 4096
#define QKV_ELEMS (BATCH * NHEAD * SEQ * HDIM)   // 3,145,728

// Scratch (no cudaMalloc allowed)
__device__ float g_q[QKV_ELEMS];
__device__ float g_k[QKV_ELEMS];
__device__ float g_v[QKV_ELEMS];
__device__ float g_attn[RTOT * CDIM];

// ---------------------------------------------------------------------------
// GEMM core: C[r,c] = sum_k A[r,k] * W[c,k]
// Block tile 128x128, K-tile 16, 256 threads, 8x8 per thread (2x2 of 4x4).
// Smem stored transposed [k][row] with stride 132 for vectorized LDS.128.
// ---------------------------------------------------------------------------

__global__ __launch_bounds__(256) void proj_qkv_kernel(
    const float* __restrict__ x, const float* __restrict__ y,
    const float* __restrict__ yw,
    const float* __restrict__ Wq, const float* __restrict__ Wk,
    const float* __restrict__ Wv)
{
    const int z = blockIdx.z;
    const float* __restrict__ A = (z == 0) ? x : y;
    const float* __restrict__ W = (z == 0) ? Wq : (z == 1) ? Wk : Wv;
    float* __restrict__ O = (z == 0) ? g_q : (z == 1) ? g_k : g_v;

    __shared__ float sA[16 * 132];
    __shared__ float sB[16 * 132];

    const int tid = threadIdx.x;
    const int tx = tid & 15;
    const int ty = tid >> 4;
    const int n0 = blockIdx.x * 128;
    const int row0 = blockIdx.y * 128;

    float acc[8][8];
#pragma unroll
    for (int i = 0; i < 8; i++)
#pragma unroll
        for (int j = 0; j < 8; j++) acc[i][j] = 0.f;

    for (int k0 = 0; k0 < CDIM; k0 += 16) {
#pragma unroll
        for (int t = 0; t < 2; t++) {
            int idx = tid + 256 * t;          // 0..511
            int row = idx >> 2;               // 0..127
            int k4  = (idx & 3) * 4;          // 0,4,8,12
            float4 va = *(const float4*)&A[(row0 + row) * CDIM + k0 + k4];
            sA[(k4 + 0) * 132 + row] = va.x;
            sA[(k4 + 1) * 132 + row] = va.y;
            sA[(k4 + 2) * 132 + row] = va.z;
            sA[(k4 + 3) * 132 + row] = va.w;
            float4 vb = *(const float4*)&W[(n0 + row) * CDIM + k0 + k4];
            sB[(k4 + 0) * 132 + row] = vb.x;
            sB[(k4 + 1) * 132 + row] = vb.y;
            sB[(k4 + 2) * 132 + row] = vb.z;
            sB[(k4 + 3) * 132 + row] = vb.w;
        }
        __syncthreads();

#pragma unroll
        for (int kk = 0; kk < 16; kk++) {
            float4 a0 = *(const float4*)&sA[kk * 132 + ty * 4];
            float4 a1 = *(const float4*)&sA[kk * 132 + 64 + ty * 4];
            float4 b0 = *(const float4*)&sB[kk * 132 + tx * 4];
            float4 b1 = *(const float4*)&sB[kk * 132 + 64 + tx * 4];
            float ar[8] = {a0.x, a0.y, a0.z, a0.w, a1.x, a1.y, a1.z, a1.w};
            float br[8] = {b0.x, b0.y, b0.z, b0.w, b1.x, b1.y, b1.z, b1.w};
#pragma unroll
            for (int i = 0; i < 8; i++)
#pragma unroll
                for (int j = 0; j < 8; j++)
                    acc[i][j] = fmaf(ar[i], br[j], acc[i][j]);
        }
        __syncthreads();
    }

    // Epilogue: write to [B, H, N, D] layout; add yw row bias for K (z==1)
#pragma unroll
    for (int ii = 0; ii < 2; ii++)
#pragma unroll
        for (int i = 0; i < 4; i++) {
            int r = row0 + ii * 64 + ty * 4 + i;
            int b = r >> 10;
            int n = r & 1023;
            float rbias = (z == 1) ? yw[r] : 0.f;
#pragma unroll
            for (int jj = 0; jj < 2; jj++) {
                int c = n0 + jj * 64 + tx * 4;
                int h = c >> 6;
                int d = c & 63;
                float4 o;
                o.x = acc[ii * 4 + i][jj * 4 + 0] + rbias;
                o.y = acc[ii * 4 + i][jj * 4 + 1] + rbias;
                o.z = acc[ii * 4 + i][jj * 4 + 2] + rbias;
                o.w = acc[ii * 4 + i][jj * 4 + 3] + rbias;
                *(float4*)&O[(((b * NHEAD + h) * SEQ) + n) * HDIM + d] = o;
            }
        }
}

__global__ __launch_bounds__(256) void proj_out_kernel(
    const float* __restrict__ Wp, const float* __restrict__ bp,
    float* __restrict__ out)
{
    const float* __restrict__ A = g_attn;
    __shared__ float sA[16 * 132];
    __shared__ float sB[16 * 132];

    const int tid = threadIdx.x;
    const int tx = tid & 15;
    const int ty = tid >> 4;
    const int n0 = blockIdx.x * 128;
    const int row0 = blockIdx.y * 128;

    float acc[8][8];
#pragma unroll
    for (int i = 0; i < 8; i++)
#pragma unroll
        for (int j = 0; j < 8; j++) acc[i][j] = 0.f;

    for (int k0 = 0; k0 < CDIM; k0 += 16) {
#pragma unroll
        for (int t = 0; t < 2; t++) {
            int idx = tid + 256 * t;
            int row = idx >> 2;
            int k4  = (idx & 3) * 4;
            float4 va = *(const float4*)&A[(row0 + row) * CDIM + k0 + k4];
            sA[(k4 + 0) * 132 + row] = va.x;
            sA[(k4 + 1) * 132 + row] = va.y;
            sA[(k4 + 2) * 132 + row] = va.z;
            sA[(k4 + 3) * 132 + row] = va.w;
            float4 vb = *(const float4*)&Wp[(n0 + row) * CDIM + k0 + k4];
            sB[(k4 + 0) * 132 + row] = vb.x;
            sB[(k4 + 1) * 132 + row] = vb.y;
            sB[(k4 + 2) * 132 + row] = vb.z;
            sB[(k4 + 3) * 132 + row] = vb.w;
        }
        __syncthreads();

#pragma unroll
        for (int kk = 0; kk < 16; kk++) {
            float4 a0 = *(const float4*)&sA[kk * 132 + ty * 4];
            float4 a1 = *(const float4*)&sA[kk * 132 + 64 + ty * 4];
            float4 b0 = *(const float4*)&sB[kk * 132 + tx * 4];
            float4 b1 = *(const float4*)&sB[kk * 132 + 64 + tx * 4];
            float ar[8] = {a0.x, a0.y, a0.z, a0.w, a1.x, a1.y, a1.z, a1.w};
            float br[8] = {b0.x, b0.y, b0.z, b0.w, b1.x, b1.y, b1.z, b1.w};
#pragma unroll
            for (int i = 0; i < 8; i++)
#pragma unroll
                for (int j = 0; j < 8; j++)
                    acc[i][j] = fmaf(ar[i], br[j], acc[i][j]);
        }
        __syncthreads();
    }

#pragma unroll
    for (int ii = 0; ii < 2; ii++)
#pragma unroll
        for (int i = 0; i < 4; i++) {
            int r = row0 + ii * 64 + ty * 4 + i;
#pragma unroll
            for (int jj = 0; jj < 2; jj++) {
                int c = n0 + jj * 64 + tx * 4;
                float4 bv = *(const float4*)&bp[c];
                float4 o;
                o.x = acc[ii * 4 + i][jj * 4 + 0] + bv.x;
                o.y = acc[ii * 4 + i][jj * 4 + 1] + bv.y;
                o.z = acc[ii * 4 + i][jj * 4 + 2] + bv.z;
                o.w = acc[ii * 4 + i][jj * 4 + 3] + bv.w;
                *(float4*)&out[r * CDIM + c] = o;
            }
        }
}

// ---------------------------------------------------------------------------
// Flash attention, fp32. One block = (b, h, 64-query tile).
// Strided 4x4 microtiles: rows r = ty + 16*i, cols c = tx + 16*j, so Ks/Qs
// LDS.128 reads are conflict-free (addr mod 8 = tx + d4).
// ---------------------------------------------------------------------------
#define SMEM_STRIDE 68           // 64 + 4 pad; *4B = 272 = 17*16 (f4 aligned)
#define ATTN_SMEM_BYTES (4 * 64 * SMEM_STRIDE * 4)   // Qs,Ks,Vs,Ps = 69632 B

__global__ __launch_bounds__(256) void attn_kernel()
{
    extern __shared__ float smem[];
    float* Qs = smem;
    float* Ks = smem + 64 * SMEM_STRIDE;
    float* Vs = smem + 2 * 64 * SMEM_STRIDE;
    float* Ps = smem + 3 * 64 * SMEM_STRIDE;

    const int tid = threadIdx.x;
    const int tx = tid & 15;
    const int ty = tid >> 4;
    const int n0 = blockIdx.x * 64;
    const int h = blockIdx.y;
    const int b = blockIdx.z;

    const float* __restrict__ Qg = g_q + ((b * NHEAD + h) * SEQ + n0) * HDIM;
    const float* __restrict__ Kg = g_k + ((b * NHEAD + h) * SEQ) * HDIM;
    const float* __restrict__ Vg = g_v + ((b * NHEAD + h) * SEQ) * HDIM;

    const float SC = 0.125f;   // 1/sqrt(64)

    // Load + pre-scale Q tile (64 x 64)
#pragma unroll
    for (int t = 0; t < 4; t++) {
        int idx = tid + 256 * t;
        int row = idx >> 4;
        int d4 = (idx & 15) * 4;
        float4 v = *(const float4*)&Qg[row * HDIM + d4];
        v.x *= SC; v.y *= SC; v.z *= SC; v.w *= SC;
        *(float4*)&Qs[row * SMEM_STRIDE + d4] = v;
    }

    float mrun[4], lrun[4], Oacc[4][4];
#pragma unroll
    for (int i = 0; i < 4; i++) {
        mrun[i] = -1e30f; lrun[i] = 0.f;
#pragma unroll
        for (int j = 0; j < 4; j++) Oacc[i][j] = 0.f;
    }

    for (int m0 = 0; m0 < SEQ; m0 += 64) {
        __syncthreads();   // prev PV reads done; also covers initial Q load
#pragma unroll
        for (int t = 0; t < 4; t++) {
            int idx = tid + 256 * t;
            int row = idx >> 4;
            int d4 = (idx & 15) * 4;
            *(float4*)&Ks[row * SMEM_STRIDE + d4] =
                *(const float4*)&Kg[(m0 + row) * HDIM + d4];
            *(float4*)&Vs[row * SMEM_STRIDE + d4] =
                *(const float4*)&Vg[(m0 + row) * HDIM + d4];
        }
        __syncthreads();

        // S = (Q*SC) K^T
        float s[4][4];
#pragma unroll
        for (int i = 0; i < 4; i++)
#pragma unroll
            for (int j = 0; j < 4; j++) s[i][j] = 0.f;

#pragma unroll
        for (int d4 = 0; d4 < 16; d4++) {
            float4 a[4], kb[4];
#pragma unroll
            for (int i = 0; i < 4; i++)
                a[i] = *(const float4*)&Qs[(ty + 16 * i) * SMEM_STRIDE + d4 * 4];
#pragma unroll
            for (int j = 0; j < 4; j++)
                kb[j] = *(const float4*)&Ks[(tx + 16 * j) * SMEM_STRIDE + d4 * 4];
#pragma unroll
            for (int i = 0; i < 4; i++)
#pragma unroll
                for (int j = 0; j < 4; j++) {
                    s[i][j] = fmaf(a[i].x, kb[j].x, s[i][j]);
                    s[i][j] = fmaf(a[i].y, kb[j].y, s[i][j]);
                    s[i][j] = fmaf(a[i].z, kb[j].z, s[i][j]);
                    s[i][j] = fmaf(a[i].w, kb[j].w, s[i][j]);
                }
        }

        // online softmax update (row reduce across 16 tx lanes)
        float corr[4];
#pragma unroll
        for (int i = 0; i < 4; i++) {
            float rmax = fmaxf(fmaxf(s[i][0], s[i][1]), fmaxf(s[i][2], s[i][3]));
#pragma unroll
            for (int off = 8; off >= 1; off >>= 1)
                rmax = fmaxf(rmax, __shfl_xor_sync(0xffffffffu, rmax, off));
            float mn = fmaxf(mrun[i], rmax);
            corr[i] = __expf(mrun[i] - mn);
            mrun[i] = mn;
            float su = 0.f;
#pragma unroll
            for (int j = 0; j < 4; j++) {
                s[i][j] = __expf(s[i][j] - mn);
                su += s[i][j];
            }
#pragma unroll
            for (int off = 8; off >= 1; off >>= 1)
                su += __shfl_xor_sync(0xffffffffu, su, off);
            lrun[i] = lrun[i] * corr[i] + su;
        }

        // stage P to smem
#pragma unroll
        for (int i = 0; i < 4; i++)
#pragma unroll
            for (int j = 0; j < 4; j++)
                Ps[(ty + 16 * i) * SMEM_STRIDE + tx + 16 * j] = s[i][j];
        __syncthreads();

        // O = O*corr + P V
#pragma unroll
        for (int i = 0; i < 4; i++)
#pragma unroll
            for (int j = 0; j < 4; j++) Oacc[i][j] *= corr[i];

#pragma unroll 8
        for (int c = 0; c < 64; c++) {
            float p[4], vv[4];
#pragma unroll
            for (int i = 0; i < 4; i++)
                p[i] = Ps[(ty + 16 * i) * SMEM_STRIDE + c];
#pragma unroll
            for (int j = 0; j < 4; j++)
                vv[j] = Vs[c * SMEM_STRIDE + tx + 16 * j];
#pragma unroll
            for (int i = 0; i < 4; i++)
#pragma unroll
                for (int j = 0; j < 4; j++)
                    Oacc[i][j] = fmaf(p[i], vv[j], Oacc[i][j]);
        }
    }

    // normalize + write to [B, N, C] (head-interleaved) for final projection
    float* __restrict__ Og = g_attn + (b * SEQ + n0) * CDIM + h * HDIM;
#pragma unroll
    for (int i = 0; i < 4; i++) {
        float inv = 1.f / lrun[i];
#pragma unroll
        for (int j = 0; j < 4; j++)
            Og[(ty + 16 * i) * CDIM + tx + 16 * j] = Oacc[i][j] * inv;
    }
}

// ---------------------------------------------------------------------------

extern "C" void kernel_launch(void* const* d_in, const int* in_sizes, int n_in,
                              void* d_out, int out_size)
{
    const float* x  = (const float*)d_in[0];
    const float* y  = (const float*)d_in[1];
    const float* yw = (const float*)d_in[2];
    const float* Wq = (const float*)d_in[3];
    const float* Wk = (const float*)d_in[4];
    const float* Wv = (const float*)d_in[5];
    const float* Wp = (const float*)d_in[6];
    const float* bp = (const float*)d_in[7];
    float* out = (float*)d_out;

    cudaFuncSetAttribute(attn_kernel,
                         cudaFuncAttributeMaxDynamicSharedMemorySize,
                         ATTN_SMEM_BYTES);

    // Q/K/V projections (one launch, z selects matrix)
    proj_qkv_kernel<<<dim3(CDIM / 128, RTOT / 128, 3), 256>>>(x, y, yw, Wq, Wk, Wv);

    // attention: (query tile, head, batch)
    attn_kernel<<<dim3(SEQ / 64, NHEAD, BATCH), 256, ATTN_SMEM_BYTES>>>();

    // output projection + bias
    proj_out_kernel<<<dim3(CDIM / 128, RTOT / 128, 1), 256>>>(Wp, bp, out);
}

// round 14
// speedup vs baseline: 1.8077x; 1.8077x over previous
#include <cuda_runtime.h>
#include <cuda_bf16.h>
#include <cstdint>

// ---------------------------------------------------------------------------
// Problem constants
// ---------------------------------------------------------------------------
#define BATCH 4
#define SEQ   1024
#define CDIM  768
#define NHEAD 12
#define HDIM  64
#define RTOT  (BATCH * SEQ)              // 4096
#define QKV_ELEMS (RTOT * CDIM)          // 3,145,728
#define W_ELEMS   (CDIM * CDIM)          // 589,824

// ---------------------------------------------------------------------------
// Scratch (static device globals; no runtime allocation allowed)
// ---------------------------------------------------------------------------
__device__ __align__(16) __nv_bfloat16 g_xh[QKV_ELEMS], g_xl[QKV_ELEMS];
__device__ __align__(16) __nv_bfloat16 g_yh[QKV_ELEMS], g_yl[QKV_ELEMS];
__device__ __align__(16) __nv_bfloat16 g_qh[QKV_ELEMS], g_ql[QKV_ELEMS];
__device__ __align__(16) __nv_bfloat16 g_kh[QKV_ELEMS], g_kl[QKV_ELEMS];
__device__ __align__(16) __nv_bfloat16 g_vh[QKV_ELEMS], g_vl[QKV_ELEMS];
__device__ __align__(16) __nv_bfloat16 g_ah[QKV_ELEMS], g_al[QKV_ELEMS];
__device__ __align__(16) __nv_bfloat16 g_wqh[W_ELEMS], g_wql[W_ELEMS];
__device__ __align__(16) __nv_bfloat16 g_wkh[W_ELEMS], g_wkl[W_ELEMS];
__device__ __align__(16) __nv_bfloat16 g_wvh[W_ELEMS], g_wvl[W_ELEMS];
__device__ __align__(16) __nv_bfloat16 g_wph[W_ELEMS], g_wpl[W_ELEMS];

// ---------------------------------------------------------------------------
// PTX helpers (sm_80-era: mma.sync / ldmatrix / cp.async — no 'a' target)
// ---------------------------------------------------------------------------
__device__ __forceinline__ uint32_t smem_u32(const void* p) {
    uint32_t a;
    asm("{ .reg .u64 t; cvta.to.shared.u64 t, %1; cvt.u32.u64 %0, t; }"
        : "=r"(a) : "l"(p));
    return a;
}

__device__ __forceinline__ void cp16(uint32_t dst, const void* src) {
    asm volatile("cp.async.cg.shared.global [%0], [%1], 16;"
                 :: "r"(dst), "l"(src));
}
#define CP_COMMIT() asm volatile("cp.async.commit_group;")
#define CP_WAIT(n)  asm volatile("cp.async.wait_group %0;" :: "n"(n))

__device__ __forceinline__ void ldsm4(uint32_t& r0, uint32_t& r1,
                                      uint32_t& r2, uint32_t& r3, uint32_t a) {
    asm volatile("ldmatrix.sync.aligned.m8n8.x4.shared.b16 {%0,%1,%2,%3}, [%4];"
                 : "=r"(r0), "=r"(r1), "=r"(r2), "=r"(r3) : "r"(a));
}
__device__ __forceinline__ void ldsm4t(uint32_t& r0, uint32_t& r1,
                                       uint32_t& r2, uint32_t& r3, uint32_t a) {
    asm volatile("ldmatrix.sync.aligned.m8n8.x4.trans.shared.b16 {%0,%1,%2,%3}, [%4];"
                 : "=r"(r0), "=r"(r1), "=r"(r2), "=r"(r3) : "r"(a));
}

// D(16x8,f32) += A(16x16 row, bf16) * B(16x8 col, bf16)
__device__ __forceinline__ void mma16816(float* d, const uint32_t* a,
                                         const uint32_t* b) {
    asm volatile(
        "mma.sync.aligned.m16n8k16.row.col.f32.bf16.bf16.f32 "
        "{%0,%1,%2,%3}, {%4,%5,%6,%7}, {%8,%9}, {%0,%1,%2,%3};"
        : "+f"(d[0]), "+f"(d[1]), "+f"(d[2]), "+f"(d[3])
        : "r"(a[0]), "r"(a[1]), "r"(a[2]), "r"(a[3]), "r"(b[0]), "r"(b[1]));
}

__device__ __forceinline__ uint32_t pack_hi(float a, float b, uint32_t& lo) {
    __nv_bfloat16 ha = __float2bfloat16(a);
    __nv_bfloat16 hb = __float2bfloat16(b);
    __nv_bfloat162 h2; h2.x = ha; h2.y = hb;
    __nv_bfloat162 l2;
    l2.x = __float2bfloat16(a - __bfloat162float(ha));
    l2.y = __float2bfloat16(b - __bfloat162float(hb));
    lo = *(uint32_t*)&l2;
    return *(uint32_t*)&h2;
}

// ---------------------------------------------------------------------------
// fp32 -> (bf16 hi, bf16 lo) split conversion
// ---------------------------------------------------------------------------
__global__ __launch_bounds__(256) void cvt_kernel(const float* __restrict__ src,
                                                  int which)
{
    __nv_bfloat16 *hi, *lo;
    switch (which) {
        case 0: hi = g_xh;  lo = g_xl;  break;
        case 1: hi = g_yh;  lo = g_yl;  break;
        case 2: hi = g_wqh; lo = g_wql; break;
        case 3: hi = g_wkh; lo = g_wkl; break;
        case 4: hi = g_wvh; lo = g_wvl; break;
        default: hi = g_wph; lo = g_wpl; break;
    }
    int i = blockIdx.x * blockDim.x + threadIdx.x;
    float4 f = ((const float4*)src)[i];
    uint32_t l0, l1;
    uint32_t h0 = pack_hi(f.x, f.y, l0);
    uint32_t h1 = pack_hi(f.z, f.w, l1);
    uint2 hv; hv.x = h0; hv.y = h1;
    uint2 lv; lv.x = l0; lv.y = l1;
    ((uint2*)hi)[i] = hv;
    ((uint2*)lo)[i] = lv;
}

// ---------------------------------------------------------------------------
// Projection GEMM (mma.sync bf16 split x3):
//   C[4096 x 768] = A[4096 x 768] * W[768 x 768]^T
// Block 128x128, ktile 32, 8 warps (warp tile 64x32), cp.async double buffer.
// which: 0=Q (x*Wq, scale 1/8, out bf16 hi/lo [B,H,N,D])
//        1=K (y*Wk, +yw row bias, out bf16 hi/lo)
//        2=V (y*Wv, out bf16 hi/lo)
//        3=proj_out (a*Wp + bp, out fp32 [RTOT, CDIM])
// ---------------------------------------------------------------------------
#define PJ_STRIDE 40
#define PJ_MAT    (128 * PJ_STRIDE)       // elems per matrix tile
#define PJ_STAGE  (4 * PJ_MAT)            // Ah, Al, Bh, Bl
#define PJ_SMEM_BYTES (2 * PJ_STAGE * 2)  // 81920 B

__global__ __launch_bounds__(256) void proj_tc(
    int which, const float* __restrict__ yw, const float* __restrict__ bp,
    float* __restrict__ dout)
{
    extern __shared__ __nv_bfloat16 sm[];
    const uint32_t sbase = smem_u32(sm);
    const int tid = threadIdx.x;
    const int wid = tid >> 5;
    const int lane = tid & 31;
    const int wm = wid & 1;       // 2 warps along M (64 rows each)
    const int wn = wid >> 1;      // 4 warps along N (32 cols each)
    const int n0 = blockIdx.x * 128;
    const int row0 = blockIdx.y * 128;

    const __nv_bfloat16 *Agh, *Agl, *Bgh, *Bgl;
    switch (which) {
        case 0: Agh = g_xh; Agl = g_xl; Bgh = g_wqh; Bgl = g_wql; break;
        case 1: Agh = g_yh; Agl = g_yl; Bgh = g_wkh; Bgl = g_wkl; break;
        case 2: Agh = g_yh; Agl = g_yl; Bgh = g_wvh; Bgl = g_wvl; break;
        default: Agh = g_ah; Agl = g_al; Bgh = g_wph; Bgl = g_wpl; break;
    }
    const __nv_bfloat16* srcs[4] = {Agh, Agl, Bgh, Bgl};

    float c[4][4][4];
#pragma unroll
    for (int i = 0; i < 4; i++)
#pragma unroll
        for (int j = 0; j < 4; j++)
#pragma unroll
            for (int r = 0; r < 4; r++) c[i][j][r] = 0.f;

    // --- async load of one ktile (32 cols) into stage ---
    auto issue = [&](int kt, int stage) {
#pragma unroll
        for (int i = 0; i < 8; i++) {
            int u = tid + 256 * i;          // 0..2047
            int mat = u >> 9;               // 512 chunks per matrix
            int v = u & 511;
            int row = v >> 2;
            int quad = v & 3;               // 16B chunk -> 8 bf16 cols
            int grow = (mat < 2 ? row0 : n0) + row;
            const __nv_bfloat16* g = srcs[mat] + grow * CDIM + kt * 32 + quad * 8;
            uint32_t s = sbase +
                (uint32_t)(stage * PJ_STAGE + mat * PJ_MAT + row * PJ_STRIDE + quad * 8) * 2;
            cp16(s, g);
        }
        CP_COMMIT();
    };

    auto compute = [&](int stage) {
        const uint32_t sa = sbase + (uint32_t)(stage * PJ_STAGE) * 2;
#pragma unroll
        for (int ks = 0; ks < 2; ks++) {
            uint32_t a[2][4][4];    // [split][mtile][reg]
            uint32_t b[2][4][2];    // [split][ntile][reg]
#pragma unroll
            for (int sp = 0; sp < 2; sp++) {
                uint32_t base = sa + (uint32_t)(sp * PJ_MAT) * 2;
#pragma unroll
                for (int mt = 0; mt < 4; mt++) {
                    int r = wm * 64 + mt * 16 + (lane & 15);
                    int col = ks * 16 + ((lane >> 4) << 3);
                    ldsm4(a[sp][mt][0], a[sp][mt][1], a[sp][mt][2], a[sp][mt][3],
                          base + (uint32_t)(r * PJ_STRIDE + col) * 2);
                }
                base = sa + (uint32_t)((2 + sp) * PJ_MAT) * 2;
#pragma unroll
                for (int p = 0; p < 2; p++) {
                    int r = wn * 32 + p * 16 + ((lane >> 4) << 3) + (lane & 7);
                    int col = ks * 16 + (((lane >> 3) & 1) << 3);
                    uint32_t r0, r1, r2, r3;
                    ldsm4(r0, r1, r2, r3, base + (uint32_t)(r * PJ_STRIDE + col) * 2);
                    b[sp][2 * p][0] = r0;     b[sp][2 * p][1] = r1;
                    b[sp][2 * p + 1][0] = r2; b[sp][2 * p + 1][1] = r3;
                }
            }
#pragma unroll
            for (int mt = 0; mt < 4; mt++)
#pragma unroll
                for (int nt = 0; nt < 4; nt++) {
                    mma16816(c[mt][nt], a[0][mt], b[0][nt]);
                    mma16816(c[mt][nt], a[1][mt], b[0][nt]);
                    mma16816(c[mt][nt], a[0][mt], b[1][nt]);
                }
        }
    };

    issue(0, 0);
    for (int kt = 0; kt < 24; kt++) {
        if (kt + 1 < 24) { issue(kt + 1, (kt + 1) & 1); CP_WAIT(1); }
        else             { CP_WAIT(0); }
        __syncthreads();
        compute(kt & 1);
        __syncthreads();
    }

    // --- epilogue ---
    const float scale = (which == 0) ? 0.125f : 1.0f;
#pragma unroll
    for (int mt = 0; mt < 4; mt++) {
#pragma unroll
        for (int rr = 0; rr < 2; rr++) {
            int r = row0 + wm * 64 + mt * 16 + (lane >> 2) + rr * 8;
            float rb = (which == 1) ? yw[r] : 0.f;
#pragma unroll
            for (int nt = 0; nt < 4; nt++) {
                int n = n0 + wn * 32 + nt * 8 + 2 * (lane & 3);
                float v0 = c[mt][nt][2 * rr]     * scale + rb;
                float v1 = c[mt][nt][2 * rr + 1] * scale + rb;
                if (which == 3) {
                    float2 o; o.x = v0 + bp[n]; o.y = v1 + bp[n + 1];
                    *(float2*)&dout[r * CDIM + n] = o;
                } else {
                    __nv_bfloat16 *hi, *lo;
                    if (which == 0)      { hi = g_qh; lo = g_ql; }
                    else if (which == 1) { hi = g_kh; lo = g_kl; }
                    else                 { hi = g_vh; lo = g_vl; }
                    int b = r >> 10, nn = r & 1023;
                    int h = n >> 6, d = n & 63;
                    long off = ((long)(b * NHEAD + h) * SEQ + nn) * HDIM + d;
                    uint32_t lw;
                    uint32_t hw = pack_hi(v0, v1, lw);
                    *(uint32_t*)&hi[off] = hw;
                    *(uint32_t*)&lo[off] = lw;
                }
            }
        }
    }
}

// ---------------------------------------------------------------------------
// Flash attention with mma.sync. Block = 128 queries x (b, h); 8 warps,
// each warp owns 16 query rows. 64-key chunks double-buffered via cp.async.
// S and P stay in registers; P is split bf16 hi/lo (3-mma PV).
// ---------------------------------------------------------------------------
#define AT_STRIDE 72
#define AT_MAT (64 * AT_STRIDE)
#define AT_STAGE (4 * AT_MAT)             // Kh, Kl, Vh, Vl
#define AT_SMEM_BYTES (2 * AT_STAGE * 2)  // 73728 B

__global__ __launch_bounds__(256) void attn_tc()
{
    extern __shared__ __nv_bfloat16 sm[];
    const uint32_t sbase = smem_u32(sm);
    const int tid = threadIdx.x;
    const int wid = tid >> 5;
    const int lane = tid & 31;
    const int q0 = blockIdx.x * 128;
    const int h = blockIdx.y;
    const int b = blockIdx.z;

    const long hb = (long)(b * NHEAD + h) * SEQ * HDIM;
    const __nv_bfloat16* __restrict__ qh = g_qh + hb;
    const __nv_bfloat16* __restrict__ ql = g_ql + hb;
    const __nv_bfloat16* srcs[4] = {g_kh + hb, g_kl + hb, g_vh + hb, g_vl + hb};

    // Load persistent Q fragments (warp rows q0 + wid*16 .. +15)
    const int qr = q0 + wid * 16;
    uint32_t qa[2][4][4];   // [split][kstep(d)][reg]
#pragma unroll
    for (int ks = 0; ks < 4; ks++) {
        int r0 = qr + (lane >> 2);
        int col = ks * 16 + 2 * (lane & 3);
        qa[0][ks][0] = *(const uint32_t*)&qh[r0 * HDIM + col];
        qa[0][ks][1] = *(const uint32_t*)&qh[(r0 + 8) * HDIM + col];
        qa[0][ks][2] = *(const uint32_t*)&qh[r0 * HDIM + col + 8];
        qa[0][ks][3] = *(const uint32_t*)&qh[(r0 + 8) * HDIM + col + 8];
        qa[1][ks][0] = *(const uint32_t*)&ql[r0 * HDIM + col];
        qa[1][ks][1] = *(const uint32_t*)&ql[(r0 + 8) * HDIM + col];
        qa[1][ks][2] = *(const uint32_t*)&ql[r0 * HDIM + col + 8];
        qa[1][ks][3] = *(const uint32_t*)&ql[(r0 + 8) * HDIM + col + 8];
    }

    float o[8][4];
#pragma unroll
    for (int i = 0; i < 8; i++)
#pragma unroll
        for (int r = 0; r < 4; r++) o[i][r] = 0.f;
    float m0 = -1e30f, m1 = -1e30f, l0 = 0.f, l1 = 0.f;

    auto issue = [&](int ch, int stage) {
#pragma unroll
        for (int i = 0; i < 8; i++) {
            int u = tid + 256 * i;
            int mat = u >> 9;
            int v = u & 511;
            int row = v >> 3;
            int q8 = v & 7;
            const __nv_bfloat16* g = srcs[mat] + (ch * 64 + row) * HDIM + q8 * 8;
            uint32_t s = sbase +
                (uint32_t)(stage * AT_STAGE + mat * AT_MAT + row * AT_STRIDE + q8 * 8) * 2;
            cp16(s, g);
        }
        CP_COMMIT();
    };

    issue(0, 0);
    for (int ch = 0; ch < 16; ch++) {
        if (ch + 1 < 16) { issue(ch + 1, (ch + 1) & 1); CP_WAIT(1); }
        else             { CP_WAIT(0); }
        __syncthreads();
        const uint32_t sa = sbase + (uint32_t)((ch & 1) * AT_STAGE) * 2;

        // ---- S = Q K^T (keys = this 64-key chunk) ----
        float s[8][4];
#pragma unroll
        for (int i = 0; i < 8; i++)
#pragma unroll
            for (int r = 0; r < 4; r++) s[i][r] = 0.f;

#pragma unroll
        for (int ks = 0; ks < 4; ks++) {
            uint32_t kb[2][8][2];
#pragma unroll
            for (int sp = 0; sp < 2; sp++) {
                uint32_t base = sa + (uint32_t)(sp * AT_MAT) * 2;
#pragma unroll
                for (int p = 0; p < 4; p++) {
                    int r = p * 16 + ((lane >> 4) << 3) + (lane & 7);
                    int col = ks * 16 + (((lane >> 3) & 1) << 3);
                    uint32_t r0, r1, r2, r3;
                    ldsm4(r0, r1, r2, r3, base + (uint32_t)(r * AT_STRIDE + col) * 2);
                    kb[sp][2 * p][0] = r0;     kb[sp][2 * p][1] = r1;
                    kb[sp][2 * p + 1][0] = r2; kb[sp][2 * p + 1][1] = r3;
                }
            }
#pragma unroll
            for (int nt = 0; nt < 8; nt++) {
                mma16816(s[nt], qa[0][ks], kb[0][nt]);
                mma16816(s[nt], qa[1][ks], kb[0][nt]);
                mma16816(s[nt], qa[0][ks], kb[1][nt]);
            }
        }

        // ---- online softmax (rows r0 = t/4, r1 = t/4+8; 4-lane groups) ----
        float rmax0 = -1e30f, rmax1 = -1e30f;
#pragma unroll
        for (int nt = 0; nt < 8; nt++) {
            rmax0 = fmaxf(rmax0, fmaxf(s[nt][0], s[nt][1]));
            rmax1 = fmaxf(rmax1, fmaxf(s[nt][2], s[nt][3]));
        }
        rmax0 = fmaxf(rmax0, __shfl_xor_sync(0xffffffffu, rmax0, 1));
        rmax0 = fmaxf(rmax0, __shfl_xor_sync(0xffffffffu, rmax0, 2));
        rmax1 = fmaxf(rmax1, __shfl_xor_sync(0xffffffffu, rmax1, 1));
        rmax1 = fmaxf(rmax1, __shfl_xor_sync(0xffffffffu, rmax1, 2));

        float m0n = fmaxf(m0, rmax0), m1n = fmaxf(m1, rmax1);
        float c0 = __expf(m0 - m0n), c1 = __expf(m1 - m1n);
        m0 = m0n; m1 = m1n;

        uint32_t ph[8][2], pl[8][2];
        float sum0 = 0.f, sum1 = 0.f;
#pragma unroll
        for (int nt = 0; nt < 8; nt++) {
            float p0 = __expf(s[nt][0] - m0n);
            float p1 = __expf(s[nt][1] - m0n);
            float p2 = __expf(s[nt][2] - m1n);
            float p3 = __expf(s[nt][3] - m1n);
            sum0 += p0 + p1; sum1 += p2 + p3;
            ph[nt][0] = pack_hi(p0, p1, pl[nt][0]);
            ph[nt][1] = pack_hi(p2, p3, pl[nt][1]);
        }
        sum0 += __shfl_xor_sync(0xffffffffu, sum0, 1);
        sum0 += __shfl_xor_sync(0xffffffffu, sum0, 2);
        sum1 += __shfl_xor_sync(0xffffffffu, sum1, 1);
        sum1 += __shfl_xor_sync(0xffffffffu, sum1, 2);
        l0 = l0 * c0 + sum0;
        l1 = l1 * c1 + sum1;
#pragma unroll
        for (int nt = 0; nt < 8; nt++) {
            o[nt][0] *= c0; o[nt][1] *= c0;
            o[nt][2] *= c1; o[nt][3] *= c1;
        }

        // ---- O += P V ----
#pragma unroll
        for (int ks = 0; ks < 4; ks++) {
            uint32_t pA[2][4];
            pA[0][0] = ph[2 * ks][0];     pA[0][1] = ph[2 * ks][1];
            pA[0][2] = ph[2 * ks + 1][0]; pA[0][3] = ph[2 * ks + 1][1];
            pA[1][0] = pl[2 * ks][0];     pA[1][1] = pl[2 * ks][1];
            pA[1][2] = pl[2 * ks + 1][0]; pA[1][3] = pl[2 * ks + 1][1];

            uint32_t vb[2][8][2];
#pragma unroll
            for (int sp = 0; sp < 2; sp++) {
                uint32_t base = sa + (uint32_t)((2 + sp) * AT_MAT) * 2;
#pragma unroll
                for (int p = 0; p < 4; p++) {
                    int r = ks * 16 + (((lane >> 3) & 1) << 3) + (lane & 7);
                    int col = p * 16 + ((lane >> 4) << 3);
                    uint32_t r0, r1, r2, r3;
                    ldsm4t(r0, r1, r2, r3, base + (uint32_t)(r * AT_STRIDE + col) * 2);
                    vb[sp][2 * p][0] = r0;     vb[sp][2 * p][1] = r1;
                    vb[sp][2 * p + 1][0] = r2; vb[sp][2 * p + 1][1] = r3;
                }
            }
#pragma unroll
            for (int nt = 0; nt < 8; nt++) {
                mma16816(o[nt], pA[0], vb[0][nt]);
                mma16816(o[nt], pA[1], vb[0][nt]);
                mma16816(o[nt], pA[0], vb[1][nt]);
            }
        }
        __syncthreads();
    }

    // ---- normalize + store bf16 hi/lo to g_ah/g_al [B, N, C] ----
    float inv0 = 1.f / l0, inv1 = 1.f / l1;
    int r0 = qr + (lane >> 2);
#pragma unroll
    for (int nt = 0; nt < 8; nt++) {
        int d = h * HDIM + nt * 8 + 2 * (lane & 3);
        uint32_t lw;
        uint32_t hw = pack_hi(o[nt][0] * inv0, o[nt][1] * inv0, lw);
        long off0 = ((long)b * SEQ + r0) * CDIM + d;
        *(uint32_t*)&g_ah[off0] = hw;
        *(uint32_t*)&g_al[off0] = lw;
        hw = pack_hi(o[nt][2] * inv1, o[nt][3] * inv1, lw);
        long off1 = ((long)b * SEQ + r0 + 8) * CDIM + d;
        *(uint32_t*)&g_ah[off1] = hw;
        *(uint32_t*)&g_al[off1] = lw;
    }
}

// ---------------------------------------------------------------------------

extern "C" void kernel_launch(void* const* d_in, const int* in_sizes, int n_in,
                              void* d_out, int out_size)
{
    const float* x  = (const float*)d_in[0];
    const float* y  = (const float*)d_in[1];
    const float* yw = (const float*)d_in[2];
    const float* Wq = (const float*)d_in[3];
    const float* Wk = (const float*)d_in[4];
    const float* Wv = (const float*)d_in[5];
    const float* Wp = (const float*)d_in[6];
    const float* bp = (const float*)d_in[7];
    float* out = (float*)d_out;

    cudaFuncSetAttribute(proj_tc, cudaFuncAttributeMaxDynamicSharedMemorySize,
                         PJ_SMEM_BYTES);
    cudaFuncSetAttribute(attn_tc, cudaFuncAttributeMaxDynamicSharedMemorySize,
                         AT_SMEM_BYTES);

    // fp32 -> bf16 hi/lo splits
    cvt_kernel<<<QKV_ELEMS / 4 / 256, 256>>>(x, 0);
    cvt_kernel<<<QKV_ELEMS / 4 / 256, 256>>>(y, 1);
    cvt_kernel<<<W_ELEMS / 4 / 256, 256>>>(Wq, 2);
    cvt_kernel<<<W_ELEMS / 4 / 256, 256>>>(Wk, 3);
    cvt_kernel<<<W_ELEMS / 4 / 256, 256>>>(Wv, 4);
    cvt_kernel<<<W_ELEMS / 4 / 256, 256>>>(Wp, 5);

    dim3 pgrid(CDIM / 128, RTOT / 128);
    proj_tc<<<pgrid, 256, PJ_SMEM_BYTES>>>(0, yw, nullptr, nullptr);
    proj_tc<<<pgrid, 256, PJ_SMEM_BYTES>>>(1, yw, nullptr, nullptr);
    proj_tc<<<pgrid, 256, PJ_SMEM_BYTES>>>(2, yw, nullptr, nullptr);

    attn_tc<<<dim3(SEQ / 128, NHEAD, BATCH), 256, AT_SMEM_BYTES>>>();

    proj_tc<<<pgrid, 256, PJ_SMEM_BYTES>>>(3, yw, bp, out);
}

// round 15
// speedup vs baseline: 2.3977x; 1.3264x over previous
#include <cuda_runtime.h>
#include <cuda_bf16.h>
#include <cstdint>

// ---------------------------------------------------------------------------
// Problem constants
// ---------------------------------------------------------------------------
#define BATCH 4
#define SEQ   1024
#define CDIM  768
#define NHEAD 12
#define HDIM  64
#define RTOT  (BATCH * SEQ)              // 4096
#define QKV_ELEMS (RTOT * CDIM)          // 3,145,728
#define W_ELEMS   (CDIM * CDIM)          // 589,824

// ---------------------------------------------------------------------------
// Scratch (static device globals; no runtime allocation allowed)
// ---------------------------------------------------------------------------
__device__ __align__(16) __nv_bfloat16 g_xh[QKV_ELEMS], g_xl[QKV_ELEMS];
__device__ __align__(16) __nv_bfloat16 g_yh[QKV_ELEMS], g_yl[QKV_ELEMS];
__device__ __align__(16) __nv_bfloat16 g_qh[QKV_ELEMS], g_ql[QKV_ELEMS];
__device__ __align__(16) __nv_bfloat16 g_kh[QKV_ELEMS], g_kl[QKV_ELEMS];
__device__ __align__(16) __nv_bfloat16 g_vh[QKV_ELEMS], g_vl[QKV_ELEMS];
__device__ __align__(16) __nv_bfloat16 g_ah[QKV_ELEMS], g_al[QKV_ELEMS];
__device__ __align__(16) __nv_bfloat16 g_wqh[W_ELEMS], g_wql[W_ELEMS];
__device__ __align__(16) __nv_bfloat16 g_wkh[W_ELEMS], g_wkl[W_ELEMS];
__device__ __align__(16) __nv_bfloat16 g_wvh[W_ELEMS], g_wvl[W_ELEMS];
__device__ __align__(16) __nv_bfloat16 g_wph[W_ELEMS], g_wpl[W_ELEMS];

// ---------------------------------------------------------------------------
// PTX helpers (sm_80-era: mma.sync / ldmatrix / cp.async — no 'a' target)
// ---------------------------------------------------------------------------
__device__ __forceinline__ uint32_t smem_u32(const void* p) {
    uint32_t a;
    asm("{ .reg .u64 t; cvta.to.shared.u64 t, %1; cvt.u32.u64 %0, t; }"
        : "=r"(a) : "l"(p));
    return a;
}

__device__ __forceinline__ void cp16(uint32_t dst, const void* src) {
    asm volatile("cp.async.cg.shared.global [%0], [%1], 16;"
                 :: "r"(dst), "l"(src));
}
#define CP_COMMIT() asm volatile("cp.async.commit_group;")
#define CP_WAIT(n)  asm volatile("cp.async.wait_group %0;" :: "n"(n))

__device__ __forceinline__ void ldsm4(uint32_t& r0, uint32_t& r1,
                                      uint32_t& r2, uint32_t& r3, uint32_t a) {
    asm volatile("ldmatrix.sync.aligned.m8n8.x4.shared.b16 {%0,%1,%2,%3}, [%4];"
                 : "=r"(r0), "=r"(r1), "=r"(r2), "=r"(r3) : "r"(a));
}
__device__ __forceinline__ void ldsm4t(uint32_t& r0, uint32_t& r1,
                                       uint32_t& r2, uint32_t& r3, uint32_t a) {
    asm volatile("ldmatrix.sync.aligned.m8n8.x4.trans.shared.b16 {%0,%1,%2,%3}, [%4];"
                 : "=r"(r0), "=r"(r1), "=r"(r2), "=r"(r3) : "r"(a));
}

// D(16x8,f32) += A(16x16 row, bf16) * B(16x8 col, bf16)
__device__ __forceinline__ void mma16816(float* d, const uint32_t* a,
                                         const uint32_t* b) {
    asm volatile(
        "mma.sync.aligned.m16n8k16.row.col.f32.bf16.bf16.f32 "
        "{%0,%1,%2,%3}, {%4,%5,%6,%7}, {%8,%9}, {%0,%1,%2,%3};"
        : "+f"(d[0]), "+f"(d[1]), "+f"(d[2]), "+f"(d[3])
        : "r"(a[0]), "r"(a[1]), "r"(a[2]), "r"(a[3]), "r"(b[0]), "r"(b[1]));
}

__device__ __forceinline__ uint32_t pack_hi(float a, float b, uint32_t& lo) {
    __nv_bfloat16 ha = __float2bfloat16(a);
    __nv_bfloat16 hb = __float2bfloat16(b);
    __nv_bfloat162 h2; h2.x = ha; h2.y = hb;
    __nv_bfloat162 l2;
    l2.x = __float2bfloat16(a - __bfloat162float(ha));
    l2.y = __float2bfloat16(b - __bfloat162float(hb));
    lo = *(uint32_t*)&l2;
    return *(uint32_t*)&h2;
}

// ---------------------------------------------------------------------------
// Fused fp32 -> (bf16 hi, bf16 lo) split conversion for all 6 input tensors.
// Block ranges: [0,3072) x, [3072,6144) y, then 576 blocks each for
// Wq, Wk, Wv, Wp.
// ---------------------------------------------------------------------------
#define XB 3072                 // QKV_ELEMS / 4 / 256
#define WB 576                  // W_ELEMS / 4 / 256

__global__ __launch_bounds__(256) void cvt_all_kernel(
    const float* __restrict__ x, const float* __restrict__ y,
    const float* __restrict__ Wq, const float* __restrict__ Wk,
    const float* __restrict__ Wv, const float* __restrict__ Wp)
{
    int bid = blockIdx.x;
    const float* src;
    __nv_bfloat16 *hi, *lo;
    int base;
    if (bid < XB)               { src = x;  hi = g_xh;  lo = g_xl;  base = bid; }
    else if (bid < 2 * XB)      { src = y;  hi = g_yh;  lo = g_yl;  base = bid - XB; }
    else if (bid < 2 * XB + WB)     { src = Wq; hi = g_wqh; lo = g_wql; base = bid - 2 * XB; }
    else if (bid < 2 * XB + 2 * WB) { src = Wk; hi = g_wkh; lo = g_wkl; base = bid - 2 * XB - WB; }
    else if (bid < 2 * XB + 3 * WB) { src = Wv; hi = g_wvh; lo = g_wvl; base = bid - 2 * XB - 2 * WB; }
    else                            { src = Wp; hi = g_wph; lo = g_wpl; base = bid - 2 * XB - 3 * WB; }

    int i = base * 256 + threadIdx.x;
    float4 f = ((const float4*)src)[i];
    uint32_t l0, l1;
    uint32_t h0 = pack_hi(f.x, f.y, l0);
    uint32_t h1 = pack_hi(f.z, f.w, l1);
    uint2 hv; hv.x = h0; hv.y = h1;
    uint2 lv; lv.x = l0; lv.y = l1;
    ((uint2*)hi)[i] = hv;
    ((uint2*)lo)[i] = lv;
}

// ---------------------------------------------------------------------------
// Projection GEMM core (mma.sync bf16 split x3):
//   C[4096 x 768] = A[4096 x 768] * W[768 x 768]^T
// Block 128x128, ktile 32, 8 warps (warp tile 64x32), cp.async double buffer.
// ---------------------------------------------------------------------------
#define PJ_STRIDE 40
#define PJ_MAT    (128 * PJ_STRIDE)       // elems per matrix tile
#define PJ_STAGE  (4 * PJ_MAT)            // Ah, Al, Bh, Bl
#define PJ_SMEM_BYTES (2 * PJ_STAGE * 2)  // 81920 B

// Shared mainloop: accumulates into c[4][4][4]; callers handle epilogue.
__device__ __forceinline__ void proj_mainloop(
    const __nv_bfloat16* Agh, const __nv_bfloat16* Agl,
    const __nv_bfloat16* Bgh, const __nv_bfloat16* Bgl,
    __nv_bfloat16* sm, uint32_t sbase,
    int row0, int n0, float c[4][4][4])
{
    const int tid = threadIdx.x;
    const int wid = tid >> 5;
    const int lane = tid & 31;
    const int wm = wid & 1;
    const int wn = wid >> 1;
    const __nv_bfloat16* srcs[4] = {Agh, Agl, Bgh, Bgl};

    auto issue = [&](int kt, int stage) {
#pragma unroll
        for (int i = 0; i < 8; i++) {
            int u = tid + 256 * i;
            int mat = u >> 9;
            int v = u & 511;
            int row = v >> 2;
            int quad = v & 3;
            int grow = (mat < 2 ? row0 : n0) + row;
            const __nv_bfloat16* g = srcs[mat] + grow * CDIM + kt * 32 + quad * 8;
            uint32_t s = sbase +
                (uint32_t)(stage * PJ_STAGE + mat * PJ_MAT + row * PJ_STRIDE + quad * 8) * 2;
            cp16(s, g);
        }
        CP_COMMIT();
    };

    auto compute = [&](int stage) {
        const uint32_t sa = sbase + (uint32_t)(stage * PJ_STAGE) * 2;
#pragma unroll
        for (int ks = 0; ks < 2; ks++) {
            uint32_t a[2][4][4];
            uint32_t b[2][4][2];
#pragma unroll
            for (int sp = 0; sp < 2; sp++) {
                uint32_t base = sa + (uint32_t)(sp * PJ_MAT) * 2;
#pragma unroll
                for (int mt = 0; mt < 4; mt++) {
                    int r = wm * 64 + mt * 16 + (lane & 15);
                    int col = ks * 16 + ((lane >> 4) << 3);
                    ldsm4(a[sp][mt][0], a[sp][mt][1], a[sp][mt][2], a[sp][mt][3],
                          base + (uint32_t)(r * PJ_STRIDE + col) * 2);
                }
                base = sa + (uint32_t)((2 + sp) * PJ_MAT) * 2;
#pragma unroll
                for (int p = 0; p < 2; p++) {
                    int r = wn * 32 + p * 16 + ((lane >> 4) << 3) + (lane & 7);
                    int col = ks * 16 + (((lane >> 3) & 1) << 3);
                    uint32_t r0, r1, r2, r3;
                    ldsm4(r0, r1, r2, r3, base + (uint32_t)(r * PJ_STRIDE + col) * 2);
                    b[sp][2 * p][0] = r0;     b[sp][2 * p][1] = r1;
                    b[sp][2 * p + 1][0] = r2; b[sp][2 * p + 1][1] = r3;
                }
            }
#pragma unroll
            for (int mt = 0; mt < 4; mt++)
#pragma unroll
                for (int nt = 0; nt < 4; nt++) {
                    mma16816(c[mt][nt], a[0][mt], b[0][nt]);
                    mma16816(c[mt][nt], a[1][mt], b[0][nt]);
                    mma16816(c[mt][nt], a[0][mt], b[1][nt]);
                }
        }
    };

    issue(0, 0);
    for (int kt = 0; kt < 24; kt++) {
        if (kt + 1 < 24) { issue(kt + 1, (kt + 1) & 1); CP_WAIT(1); }
        else             { CP_WAIT(0); }
        __syncthreads();
        compute(kt & 1);
        __syncthreads();
    }
}

// Fused Q/K/V projection: blockIdx.z selects which (0=Q, 1=K, 2=V).
__global__ __launch_bounds__(256) void proj_qkv_tc(const float* __restrict__ yw)
{
    extern __shared__ __nv_bfloat16 sm[];
    const uint32_t sbase = smem_u32(sm);
    const int which = blockIdx.z;
    const int tid = threadIdx.x;
    const int wid = tid >> 5;
    const int lane = tid & 31;
    const int wm = wid & 1;
    const int wn = wid >> 1;
    const int n0 = blockIdx.x * 128;
    const int row0 = blockIdx.y * 128;

    const __nv_bfloat16 *Agh, *Agl, *Bgh, *Bgl;
    __nv_bfloat16 *Oh, *Ol;
    switch (which) {
        case 0:  Agh = g_xh; Agl = g_xl; Bgh = g_wqh; Bgl = g_wql; Oh = g_qh; Ol = g_ql; break;
        case 1:  Agh = g_yh; Agl = g_yl; Bgh = g_wkh; Bgl = g_wkl; Oh = g_kh; Ol = g_kl; break;
        default: Agh = g_yh; Agl = g_yl; Bgh = g_wvh; Bgl = g_wvl; Oh = g_vh; Ol = g_vl; break;
    }

    float c[4][4][4];
#pragma unroll
    for (int i = 0; i < 4; i++)
#pragma unroll
        for (int j = 0; j < 4; j++)
#pragma unroll
            for (int r = 0; r < 4; r++) c[i][j][r] = 0.f;

    proj_mainloop(Agh, Agl, Bgh, Bgl, sm, sbase, row0, n0, c);

    const float scale = (which == 0) ? 0.125f : 1.0f;
#pragma unroll
    for (int mt = 0; mt < 4; mt++) {
#pragma unroll
        for (int rr = 0; rr < 2; rr++) {
            int r = row0 + wm * 64 + mt * 16 + (lane >> 2) + rr * 8;
            float rb = (which == 1) ? yw[r] : 0.f;
#pragma unroll
            for (int nt = 0; nt < 4; nt++) {
                int n = n0 + wn * 32 + nt * 8 + 2 * (lane & 3);
                float v0 = c[mt][nt][2 * rr]     * scale + rb;
                float v1 = c[mt][nt][2 * rr + 1] * scale + rb;
                int b = r >> 10, nn = r & 1023;
                int h = n >> 6, d = n & 63;
                long off = ((long)(b * NHEAD + h) * SEQ + nn) * HDIM + d;
                uint32_t lw;
                uint32_t hw = pack_hi(v0, v1, lw);
                *(uint32_t*)&Oh[off] = hw;
                *(uint32_t*)&Ol[off] = lw;
            }
        }
    }
}

// Output projection: attn (bf16 hi/lo) * Wp^T + bp -> fp32 out.
__global__ __launch_bounds__(256) void proj_out_tc(
    const float* __restrict__ bp, float* __restrict__ dout)
{
    extern __shared__ __nv_bfloat16 sm[];
    const uint32_t sbase = smem_u32(sm);
    const int tid = threadIdx.x;
    const int wid = tid >> 5;
    const int lane = tid & 31;
    const int wm = wid & 1;
    const int wn = wid >> 1;
    const int n0 = blockIdx.x * 128;
    const int row0 = blockIdx.y * 128;

    float c[4][4][4];
#pragma unroll
    for (int i = 0; i < 4; i++)
#pragma unroll
        for (int j = 0; j < 4; j++)
#pragma unroll
            for (int r = 0; r < 4; r++) c[i][j][r] = 0.f;

    proj_mainloop(g_ah, g_al, g_wph, g_wpl, sm, sbase, row0, n0, c);

#pragma unroll
    for (int mt = 0; mt < 4; mt++) {
#pragma unroll
        for (int rr = 0; rr < 2; rr++) {
            int r = row0 + wm * 64 + mt * 16 + (lane >> 2) + rr * 8;
#pragma unroll
            for (int nt = 0; nt < 4; nt++) {
                int n = n0 + wn * 32 + nt * 8 + 2 * (lane & 3);
                float2 o;
                o.x = c[mt][nt][2 * rr]     + bp[n];
                o.y = c[mt][nt][2 * rr + 1] + bp[n + 1];
                *(float2*)&dout[r * CDIM + n] = o;
            }
        }
    }
}

// ---------------------------------------------------------------------------
// Flash attention with mma.sync. Block = 128 queries x (b, h); 8 warps,
// each warp owns 16 query rows. 64-key chunks double-buffered via cp.async.
// S and P stay in registers; P is split bf16 hi/lo (3-mma PV).
// ---------------------------------------------------------------------------
#define AT_STRIDE 72
#define AT_MAT (64 * AT_STRIDE)
#define AT_STAGE (4 * AT_MAT)             // Kh, Kl, Vh, Vl
#define AT_SMEM_BYTES (2 * AT_STAGE * 2)  // 73728 B

__global__ __launch_bounds__(256) void attn_tc()
{
    extern __shared__ __nv_bfloat16 sm[];
    const uint32_t sbase = smem_u32(sm);
    const int tid = threadIdx.x;
    const int wid = tid >> 5;
    const int lane = tid & 31;
    const int q0 = blockIdx.x * 128;
    const int h = blockIdx.y;
    const int b = blockIdx.z;

    const long hb = (long)(b * NHEAD + h) * SEQ * HDIM;
    const __nv_bfloat16* __restrict__ qh = g_qh + hb;
    const __nv_bfloat16* __restrict__ ql = g_ql + hb;
    const __nv_bfloat16* srcs[4] = {g_kh + hb, g_kl + hb, g_vh + hb, g_vl + hb};

    // Load persistent Q fragments (warp rows q0 + wid*16 .. +15)
    const int qr = q0 + wid * 16;
    uint32_t qa[2][4][4];   // [split][kstep(d)][reg]
#pragma unroll
    for (int ks = 0; ks < 4; ks++) {
        int r0 = qr + (lane >> 2);
        int col = ks * 16 + 2 * (lane & 3);
        qa[0][ks][0] = *(const uint32_t*)&qh[r0 * HDIM + col];
        qa[0][ks][1] = *(const uint32_t*)&qh[(r0 + 8) * HDIM + col];
        qa[0][ks][2] = *(const uint32_t*)&qh[r0 * HDIM + col + 8];
        qa[0][ks][3] = *(const uint32_t*)&qh[(r0 + 8) * HDIM + col + 8];
        qa[1][ks][0] = *(const uint32_t*)&ql[r0 * HDIM + col];
        qa[1][ks][1] = *(const uint32_t*)&ql[(r0 + 8) * HDIM + col];
        qa[1][ks][2] = *(const uint32_t*)&ql[r0 * HDIM + col + 8];
        qa[1][ks][3] = *(const uint32_t*)&ql[(r0 + 8) * HDIM + col + 8];
    }

    float o[8][4];
#pragma unroll
    for (int i = 0; i < 8; i++)
#pragma unroll
        for (int r = 0; r < 4; r++) o[i][r] = 0.f;
    float m0 = -1e30f, m1 = -1e30f, l0 = 0.f, l1 = 0.f;

    auto issue = [&](int ch, int stage) {
#pragma unroll
        for (int i = 0; i < 8; i++) {
            int u = tid + 256 * i;
            int mat = u >> 9;
            int v = u & 511;
            int row = v >> 3;
            int q8 = v & 7;
            const __nv_bfloat16* g = srcs[mat] + (ch * 64 + row) * HDIM + q8 * 8;
            uint32_t s = sbase +
                (uint32_t)(stage * AT_STAGE + mat * AT_MAT + row * AT_STRIDE + q8 * 8) * 2;
            cp16(s, g);
        }
        CP_COMMIT();
    };

    issue(0, 0);
    for (int ch = 0; ch < 16; ch++) {
        if (ch + 1 < 16) { issue(ch + 1, (ch + 1) & 1); CP_WAIT(1); }
        else             { CP_WAIT(0); }
        __syncthreads();
        const uint32_t sa = sbase + (uint32_t)((ch & 1) * AT_STAGE) * 2;

        // ---- S = Q K^T (keys = this 64-key chunk) ----
        float s[8][4];
#pragma unroll
        for (int i = 0; i < 8; i++)
#pragma unroll
            for (int r = 0; r < 4; r++) s[i][r] = 0.f;

#pragma unroll
        for (int ks = 0; ks < 4; ks++) {
            uint32_t kb[2][8][2];
#pragma unroll
            for (int sp = 0; sp < 2; sp++) {
                uint32_t base = sa + (uint32_t)(sp * AT_MAT) * 2;
#pragma unroll
                for (int p = 0; p < 4; p++) {
                    int r = p * 16 + ((lane >> 4) << 3) + (lane & 7);
                    int col = ks * 16 + (((lane >> 3) & 1) << 3);
                    uint32_t r0, r1, r2, r3;
                    ldsm4(r0, r1, r2, r3, base + (uint32_t)(r * AT_STRIDE + col) * 2);
                    kb[sp][2 * p][0] = r0;     kb[sp][2 * p][1] = r1;
                    kb[sp][2 * p + 1][0] = r2; kb[sp][2 * p + 1][1] = r3;
                }
            }
#pragma unroll
            for (int nt = 0; nt < 8; nt++) {
                mma16816(s[nt], qa[0][ks], kb[0][nt]);
                mma16816(s[nt], qa[1][ks], kb[0][nt]);
                mma16816(s[nt], qa[0][ks], kb[1][nt]);
            }
        }

        // ---- online softmax (rows r0 = t/4, r1 = t/4+8; 4-lane groups) ----
        float rmax0 = -1e30f, rmax1 = -1e30f;
#pragma unroll
        for (int nt = 0; nt < 8; nt++) {
            rmax0 = fmaxf(rmax0, fmaxf(s[nt][0], s[nt][1]));
            rmax1 = fmaxf(rmax1, fmaxf(s[nt][2], s[nt][3]));
        }
        rmax0 = fmaxf(rmax0, __shfl_xor_sync(0xffffffffu, rmax0, 1));
        rmax0 = fmaxf(rmax0, __shfl_xor_sync(0xffffffffu, rmax0, 2));
        rmax1 = fmaxf(rmax1, __shfl_xor_sync(0xffffffffu, rmax1, 1));
        rmax1 = fmaxf(rmax1, __shfl_xor_sync(0xffffffffu, rmax1, 2));

        float m0n = fmaxf(m0, rmax0), m1n = fmaxf(m1, rmax1);
        float c0 = __expf(m0 - m0n), c1 = __expf(m1 - m1n);
        m0 = m0n; m1 = m1n;

        uint32_t ph[8][2], pl[8][2];
        float sum0 = 0.f, sum1 = 0.f;
#pragma unroll
        for (int nt = 0; nt < 8; nt++) {
            float p0 = __expf(s[nt][0] - m0n);
            float p1 = __expf(s[nt][1] - m0n);
            float p2 = __expf(s[nt][2] - m1n);
            float p3 = __expf(s[nt][3] - m1n);
            sum0 += p0 + p1; sum1 += p2 + p3;
            ph[nt][0] = pack_hi(p0, p1, pl[nt][0]);
            ph[nt][1] = pack_hi(p2, p3, pl[nt][1]);
        }
        sum0 += __shfl_xor_sync(0xffffffffu, sum0, 1);
        sum0 += __shfl_xor_sync(0xffffffffu, sum0, 2);
        sum1 += __shfl_xor_sync(0xffffffffu, sum1, 1);
        sum1 += __shfl_xor_sync(0xffffffffu, sum1, 2);
        l0 = l0 * c0 + sum0;
        l1 = l1 * c1 + sum1;
#pragma unroll
        for (int nt = 0; nt < 8; nt++) {
            o[nt][0] *= c0; o[nt][1] *= c0;
            o[nt][2] *= c1; o[nt][3] *= c1;
        }

        // ---- O += P V ----
#pragma unroll
        for (int ks = 0; ks < 4; ks++) {
            uint32_t pA[2][4];
            pA[0][0] = ph[2 * ks][0];     pA[0][1] = ph[2 * ks][1];
            pA[0][2] = ph[2 * ks + 1][0]; pA[0][3] = ph[2 * ks + 1][1];
            pA[1][0] = pl[2 * ks][0];     pA[1][1] = pl[2 * ks][1];
            pA[1][2] = pl[2 * ks + 1][0]; pA[1][3] = pl[2 * ks + 1][1];

            uint32_t vb[2][8][2];
#pragma unroll
            for (int sp = 0; sp < 2; sp++) {
                uint32_t base = sa + (uint32_t)((2 + sp) * AT_MAT) * 2;
#pragma unroll
                for (int p = 0; p < 4; p++) {
                    int r = ks * 16 + (((lane >> 3) & 1) << 3) + (lane & 7);
                    int col = p * 16 + ((lane >> 4) << 3);
                    uint32_t r0, r1, r2, r3;
                    ldsm4t(r0, r1, r2, r3, base + (uint32_t)(r * AT_STRIDE + col) * 2);
                    vb[sp][2 * p][0] = r0;     vb[sp][2 * p][1] = r1;
                    vb[sp][2 * p + 1][0] = r2; vb[sp][2 * p + 1][1] = r3;
                }
            }
#pragma unroll
            for (int nt = 0; nt < 8; nt++) {
                mma16816(o[nt], pA[0], vb[0][nt]);
                mma16816(o[nt], pA[1], vb[0][nt]);
                mma16816(o[nt], pA[0], vb[1][nt]);
            }
        }
        __syncthreads();
    }

    // ---- normalize + store bf16 hi/lo to g_ah/g_al [B, N, C] ----
    float inv0 = 1.f / l0, inv1 = 1.f / l1;
    int r0 = qr + (lane >> 2);
#pragma unroll
    for (int nt = 0; nt < 8; nt++) {
        int d = h * HDIM + nt * 8 + 2 * (lane & 3);
        uint32_t lw;
        uint32_t hw = pack_hi(o[nt][0] * inv0, o[nt][1] * inv0, lw);
        long off0 = ((long)b * SEQ + r0) * CDIM + d;
        *(uint32_t*)&g_ah[off0] = hw;
        *(uint32_t*)&g_al[off0] = lw;
        hw = pack_hi(o[nt][2] * inv1, o[nt][3] * inv1, lw);
        long off1 = ((long)b * SEQ + r0 + 8) * CDIM + d;
        *(uint32_t*)&g_ah[off1] = hw;
        *(uint32_t*)&g_al[off1] = lw;
    }
}

// ---------------------------------------------------------------------------

extern "C" void kernel_launch(void* const* d_in, const int* in_sizes, int n_in,
                              void* d_out, int out_size)
{
    const float* x  = (const float*)d_in[0];
    const float* y  = (const float*)d_in[1];
    const float* yw = (const float*)d_in[2];
    const float* Wq = (const float*)d_in[3];
    const float* Wk = (const float*)d_in[4];
    const float* Wv = (const float*)d_in[5];
    const float* Wp = (const float*)d_in[6];
    const float* bp = (const float*)d_in[7];
    float* out = (float*)d_out;

    cudaFuncSetAttribute(proj_qkv_tc, cudaFuncAttributeMaxDynamicSharedMemorySize,
                         PJ_SMEM_BYTES);
    cudaFuncSetAttribute(proj_out_tc, cudaFuncAttributeMaxDynamicSharedMemorySize,
                         PJ_SMEM_BYTES);
    cudaFuncSetAttribute(attn_tc, cudaFuncAttributeMaxDynamicSharedMemorySize,
                         AT_SMEM_BYTES);

    // fp32 -> bf16 hi/lo splits (one fused launch)
    cvt_all_kernel<<<2 * XB + 4 * WB, 256>>>(x, y, Wq, Wk, Wv, Wp);

    // Q/K/V projections fused into one launch (z = which)
    proj_qkv_tc<<<dim3(CDIM / 128, RTOT / 128, 3), 256, PJ_SMEM_BYTES>>>(yw);

    attn_tc<<<dim3(SEQ / 128, NHEAD, BATCH), 256, AT_SMEM_BYTES>>>();

    proj_out_tc<<<dim3(CDIM / 128, RTOT / 128), 256, PJ_SMEM_BYTES>>>(bp, out);
}